// round 16
// baseline (speedup 1.0000x reference)
#include <cuda_runtime.h>
#include <cuda_fp16.h>
#include <math_constants.h>
#include <cstdint>

#define NNODES 100000
#define NEDGES 1600000

// ---------------- scratch (static __device__ — no allocs allowed) ----------------
__device__ __half g_mh[(size_t)NNODES * 384];     // projected messages, fp16 [N][3*128]
__device__ __half g_fh[(size_t)NNODES * 1536];    // PNA features, fp16 [N][1536]
__device__ __half g_wh[3 * 128 * 128];            // W|W2|W3 TRANSPOSED [n][k], fp16
__device__ __half g_pwh[128 * 1536];              // pna_w TRANSPOSED [n=128][k=1536], fp16
__device__ int    g_rowptr[NNODES + 1];

// ---------------- cp.async helpers ----------------
__device__ __forceinline__ void cpasync16(unsigned int dst, const void* src) {
    asm volatile("cp.async.cg.shared.global [%0], [%1], 16;\n" :: "r"(dst), "l"(src));
}
__device__ __forceinline__ void cp_commit() {
    asm volatile("cp.async.commit_group;\n" ::);
}
__device__ __forceinline__ void cp_wait1() {
    asm volatile("cp.async.wait_group 1;\n" ::);
}
__device__ __forceinline__ void cp_wait0() {
    asm volatile("cp.async.wait_group 0;\n" ::);
}

// ---------------- fp16 MMA m16n8k16 + ldmatrix ----------------
__device__ __forceinline__ void mma_f16(float* d, const unsigned* a, const unsigned* b) {
    asm volatile(
        "mma.sync.aligned.m16n8k16.row.col.f32.f16.f16.f32 "
        "{%0,%1,%2,%3},{%4,%5,%6,%7},{%8,%9},{%0,%1,%2,%3};\n"
        : "+f"(d[0]), "+f"(d[1]), "+f"(d[2]), "+f"(d[3])
        : "r"(a[0]), "r"(a[1]), "r"(a[2]), "r"(a[3]), "r"(b[0]), "r"(b[1]));
}
__device__ __forceinline__ void ldmx4(unsigned& r0, unsigned& r1, unsigned& r2,
                                      unsigned& r3, unsigned addr) {
    asm volatile("ldmatrix.sync.aligned.m8n8.x4.shared.b16 {%0,%1,%2,%3}, [%4];"
                 : "=r"(r0), "=r"(r1), "=r"(r2), "=r"(r3) : "r"(addr));
}

// streaming (evict-first) stores — keep gather working set resident in L2
__device__ __forceinline__ void stcs_u2(void* p, uint2 o) {
    asm volatile("st.global.cs.v2.u32 [%0], {%1,%2};" :: "l"(p), "r"(o.x), "r"(o.y) : "memory");
}
__device__ __forceinline__ void stcs_f2(void* p, float2 v) {
    asm volatile("st.global.cs.v2.f32 [%0], {%1,%2};" :: "l"(p), "f"(v.x), "f"(v.y) : "memory");
}
// streaming (evict-first) loads for read-once edge arrays
__device__ __forceinline__ int ldcs_i(const int* p) {
    int v; asm volatile("ld.global.cs.s32 %0, [%1];" : "=r"(v) : "l"(p)); return v;
}
__device__ __forceinline__ float ldcs_f(const float* p) {
    float v; asm volatile("ld.global.cs.f32 %0, [%1];" : "=f"(v) : "l"(p)); return v;
}

// ---------------- conversion kernels ----------------
// transpose + convert the 3 projection weights: src [128][128] -> dst [n][k]
__global__ void k_cvt_w3(const float* __restrict__ W, const float* __restrict__ W2,
                         const float* __restrict__ W3, __half* __restrict__ dst) {
    const int slab = blockIdx.y;
    const float* src = (slab == 0) ? W : (slab == 1) ? W2 : W3;
    int i = blockIdx.x * blockDim.x + threadIdx.x;
    if (i < 128 * 128) {
        int k = i >> 7, n = i & 127;
        dst[slab * 16384 + n * 128 + k] = __float2half_rn(src[i]);
    }
}

// transpose + convert: src [K][Ncols] fp32 -> dst [Ncols][K] fp16
__global__ void k_cvt_t(const float* __restrict__ src, __half* __restrict__ dst,
                        int K, int Ncols) {
    int i = blockIdx.x * blockDim.x + threadIdx.x;
    if (i < K * Ncols) {
        int k = i / Ncols, n = i % Ncols;
        dst[(size_t)n * K + k] = __float2half_rn(src[i]);
    }
}

// ---------------- row pointers from sorted rows ----------------
__global__ void k_rowptr(const int* __restrict__ rows, int E, int N) {
    int i = blockIdx.x * blockDim.x + threadIdx.x;
    if (i > N) return;
    int lo = 0, hi = E;
    while (lo < hi) {
        int mid = (lo + hi) >> 1;
        if (__ldg(rows + mid) < i) lo = mid + 1; else hi = mid;
    }
    g_rowptr[i] = lo;
}

// =====================================================================
// fp16 MMA GEMM core (k_out): 128x128 block tile, 8 warps (2x4),
// 64x32 warp tiles, m16n8k16, 3-stage cp.async ring, K-chunk 32.
// =====================================================================
#define RPADH 40                        // halves per smem row (32 data + 8 pad = 80B)
#define STH   (128 * RPADH)             // halves per stage (A or B)
#define GEMM_SMEM (6 * STH * 2)         // 3 stages A + 3 stages B = 60 KB

template <int NK2, int LDA, int LDB>
__device__ __forceinline__ void gemm_fp16_core(
    const __half* __restrict__ Ag, const __half* __restrict__ Bg,
    float acc[4][4][4], int bm, int N, __half* sm) {
    __half* Asb = sm;
    __half* Bsb = sm + 3 * STH;

    const int tid = threadIdx.x;
    const int lane = tid & 31;
    const int wid = tid >> 5;
    const int wm = wid >> 2, wn = wid & 3;

    const int srow = tid >> 1;
    const int shalf = (tid & 1) * 16;

    int gr = bm + srow; if (gr >= N) gr = N - 1;
    const __half* sA = Ag + (size_t)gr * LDA + shalf;
    const __half* sB = Bg + (size_t)srow * LDB + shalf;

    const unsigned dA = (unsigned)__cvta_generic_to_shared(&Asb[srow * RPADH + shalf]);
    const unsigned dB = (unsigned)__cvta_generic_to_shared(&Bsb[srow * RPADH + shalf]);
    const unsigned Abase = (unsigned)__cvta_generic_to_shared(Asb);
    const unsigned Bbase = (unsigned)__cvta_generic_to_shared(Bsb);

    const int arow = ((lane >> 3) & 1) * 8 + (lane & 7);
    const int akof = (lane >> 4) * 8;
    unsigned aoff[4];
#pragma unroll
    for (int mt = 0; mt < 4; mt++)
        aoff[mt] = (unsigned)(((wm * 64 + mt * 16 + arow) * RPADH + akof) * 2);
    const int brow = (lane & 7) + ((lane >> 4) & 1) * 8;
    const int bkof = ((lane >> 3) & 1) * 8;
    unsigned boff[2];
#pragma unroll
    for (int p = 0; p < 2; p++)
        boff[p] = (unsigned)(((wn * 32 + p * 16 + brow) * RPADH + bkof) * 2);

#pragma unroll
    for (int p = 0; p < 2; p++) {
        cpasync16(dA + p * STH * 2, sA + p * 32);
        cpasync16(dA + p * STH * 2 + 16, sA + p * 32 + 8);
        cpasync16(dB + p * STH * 2, sB + p * 32);
        cpasync16(dB + p * STH * 2 + 16, sB + p * 32 + 8);
        cp_commit();
    }

    for (int i = 0; i < NK2; i++) {
        cp_wait1();
        __syncthreads();
        const int nc = i + 2;
        if (nc < NK2) {
            const int sl = nc - (nc / 3) * 3;
            cpasync16(dA + sl * STH * 2, sA + nc * 32);
            cpasync16(dA + sl * STH * 2 + 16, sA + nc * 32 + 8);
            cpasync16(dB + sl * STH * 2, sB + nc * 32);
            cpasync16(dB + sl * STH * 2 + 16, sB + nc * 32 + 8);
        }
        cp_commit();

        const int buf = i - (i / 3) * 3;
        const unsigned sa = Abase + buf * STH * 2;
        const unsigned sb = Bbase + buf * STH * 2;

#pragma unroll
        for (int s = 0; s < 2; s++) {
            unsigned afr[4][4], bfr[4][2];
#pragma unroll
            for (int mt = 0; mt < 4; mt++)
                ldmx4(afr[mt][0], afr[mt][1], afr[mt][2], afr[mt][3],
                      sa + aoff[mt] + s * 32);
#pragma unroll
            for (int p = 0; p < 2; p++)
                ldmx4(bfr[2 * p][0], bfr[2 * p][1], bfr[2 * p + 1][0], bfr[2 * p + 1][1],
                      sb + boff[p] + s * 32);
#pragma unroll
            for (int mt = 0; mt < 4; mt++)
#pragma unroll
                for (int nt = 0; nt < 4; nt++)
                    mma_f16(acc[mt][nt], afr[mt], bfr[nt]);
        }
    }
}

// =====================================================================
// projection GEMM v4: one block = 128 rows x ALL 3 slabs.
// A staged once from fp32 x; B per-slab RESIDENT with ping-pong
// prefetch (cp.async). 4 barriers total, 8 barrier-free k16 steps/slab.
// smem = A (34816B) + 2x B (34816B) = 104448B -> 2 blocks/SM.
// =====================================================================
#define APROW 136                        // halves per row (272B)
#define PROJ_ASZ (128 * APROW)           // halves per tile (A or one B buffer)
#define PROJ_SMEM (3 * PROJ_ASZ * 2)     // 104448 B

__global__ __launch_bounds__(256, 2) void k_proj(const float* __restrict__ x, int N) {
    extern __shared__ __align__(16) __half smh[];
    __half* Ah = smh;                    // [128][APROW]
    __half* Bh = smh + PROJ_ASZ;         // [2][128][APROW] ping-pong

    const int bm = blockIdx.x * 128;
    const int tid = threadIdx.x;
    const int lane = tid & 31;
    const int wid = tid >> 5;
    const int wm = wid >> 2, wn = wid & 3;
    const int tq = lane >> 2, tr = lane & 3;

    const unsigned Ahb = (unsigned)__cvta_generic_to_shared(Ah);
    const unsigned Bhb = (unsigned)__cvta_generic_to_shared(Bh);

    // B staging: 128 rows x 16 chunks of 16B = 2048 chunks, 8 per thread
    const int b_r0 = tid >> 1;                 // base row group: i = tid + j*256
    // stage slab s into buffer b
    auto stageB = [&](int s, int b) {
#pragma unroll
        for (int j = 0; j < 8; j++) {
            int i = tid + j * 256;             // 0..2047
            int row = i >> 4, c = i & 15;
            cpasync16(Bhb + (unsigned)((b * PROJ_ASZ + row * APROW + c * 8) * 2),
                      g_wh + s * 16384 + row * 128 + c * 8);
        }
        cp_commit();
    };
    (void)b_r0;

    // prefetch B slab 0 first (async engine works under A conversion)
    stageB(0, 0);

    // ---- stage A from fp32 x, converting to fp16 ----
#pragma unroll
    for (int j = 0; j < 16; j++) {
        int i = tid + j * 256;           // 0..4095 over 128 rows x 32 float4
        int row = i >> 5, c4 = (i & 31) << 2;
        int gr = bm + row; if (gr >= N) gr = N - 1;
        float4 v = *(const float4*)&x[(size_t)gr * 128 + c4];
        __half2 h0 = __floats2half2_rn(v.x, v.y);
        __half2 h1 = __floats2half2_rn(v.z, v.w);
        uint2 o; o.x = *(unsigned*)&h0; o.y = *(unsigned*)&h1;
        *(uint2*)&Ah[row * APROW + c4] = o;
    }
    cp_wait0();
    __syncthreads();

    // ldmatrix offsets
    const int arow = ((lane >> 3) & 1) * 8 + (lane & 7);
    const int akof = (lane >> 4) * 8;
    unsigned aoff[4];
#pragma unroll
    for (int mt = 0; mt < 4; mt++)
        aoff[mt] = (unsigned)(((wm * 64 + mt * 16 + arow) * APROW + akof) * 2);
    const int brow = (lane & 7) + ((lane >> 4) & 1) * 8;
    const int bkof = ((lane >> 3) & 1) * 8;
    unsigned boff[2];
#pragma unroll
    for (int p = 0; p < 2; p++)
        boff[p] = (unsigned)(((wn * 32 + p * 16 + brow) * APROW + bkof) * 2);

    for (int slab = 0; slab < 3; slab++) {
        const int buf = slab & 1;
        if (slab < 2) stageB(slab + 1, buf ^ 1);   // prefetch next under compute

        const unsigned sb = Bhb + (unsigned)(buf * PROJ_ASZ * 2);
        float acc[4][4][4] = {};
#pragma unroll
        for (int s = 0; s < 8; s++) {              // 8 k16 steps, no barriers
            unsigned afr[4][4], bfr[4][2];
#pragma unroll
            for (int mt = 0; mt < 4; mt++)
                ldmx4(afr[mt][0], afr[mt][1], afr[mt][2], afr[mt][3],
                      Ahb + aoff[mt] + s * 32);
#pragma unroll
            for (int p = 0; p < 2; p++)
                ldmx4(bfr[2 * p][0], bfr[2 * p][1], bfr[2 * p + 1][0],
                      bfr[2 * p + 1][1], sb + boff[p] + s * 32);
#pragma unroll
            for (int mt = 0; mt < 4; mt++)
#pragma unroll
                for (int nt = 0; nt < 4; nt++)
                    mma_f16(acc[mt][nt], afr[mt], bfr[nt]);
        }

        // epilogue for this slab (global stores only; no smem)
#pragma unroll
        for (int nt = 0; nt < 4; nt++) {
            const int c0 = slab * 128 + wn * 32 + nt * 8 + 2 * tr;
#pragma unroll
            for (int mt = 0; mt < 4; mt++) {
                const int r0 = bm + wm * 64 + mt * 16 + tq;
                if (r0 < N) {
                    __half2 h = __floats2half2_rn(acc[mt][nt][0], acc[mt][nt][1]);
                    *(__half2*)&g_mh[(size_t)r0 * 384 + c0] = h;
                }
                const int r1 = r0 + 8;
                if (r1 < N) {
                    __half2 h = __floats2half2_rn(acc[mt][nt][2], acc[mt][nt][3]);
                    *(__half2*)&g_mh[(size_t)r1 * 384 + c0] = h;
                }
            }
        }

        if (slab < 2) {
            cp_wait0();
            __syncthreads();   // next buffer ready; prior buffer reads all done
        }
    }
}

// ---------------- aggregation: warp-per-(node,channel) segment stats ----------------
__device__ __forceinline__ float4 h4tof4(uint2 u) {
    __half2 a = *(__half2*)&u.x;
    __half2 b = *(__half2*)&u.y;
    float2 fa = __half22float2(a), fb = __half22float2(b);
    return make_float4(fa.x, fa.y, fb.x, fb.y);
}

__device__ __forceinline__ void agg_upd(float4 v, float s, float4& su, float4& sq,
                                        float4& mx, float4& mn) {
    float gx = v.x * s, gy = v.y * s, gz = v.z * s, gw = v.w * s;
    su.x += gx; su.y += gy; su.z += gz; su.w += gw;
    sq.x += gx * gx; sq.y += gy * gy; sq.z += gz * gz; sq.w += gw * gw;
    mx.x = fmaxf(mx.x, gx); mx.y = fmaxf(mx.y, gy); mx.z = fmaxf(mx.z, gz); mx.w = fmaxf(mx.w, gw);
    mn.x = fminf(mn.x, gx); mn.y = fminf(mn.y, gy); mn.z = fminf(mn.z, gz); mn.w = fminf(mn.w, gw);
}

__device__ __forceinline__ void sth4_cs(__half* p, float4 v) {
    __half2 h0 = __floats2half2_rn(v.x, v.y);
    __half2 h1 = __floats2half2_rn(v.z, v.w);
    uint2 o; o.x = *(unsigned*)&h0; o.y = *(unsigned*)&h1;
    stcs_u2(p, o);
}

__global__ __launch_bounds__(256) void k_agg(const int* __restrict__ cols,
                                             const float* __restrict__ vA,
                                             const float* __restrict__ vC, int N) {
    int gw = (blockIdx.x * blockDim.x + threadIdx.x) >> 5;  // global warp
    int lane = threadIdx.x & 31;
    if (gw >= 3 * N) return;
    const int node = gw / 3;
    const int ch = gw - 3 * node;         // 0: vA, 1: vC, 2: vA*vC
    const int r0 = g_rowptr[node], r1 = g_rowptr[node + 1];

    const float NEG = -CUDART_INF_F, POS = CUDART_INF_F;
    float4 su = {0, 0, 0, 0}, sq = {0, 0, 0, 0};
    float4 mx = {NEG, NEG, NEG, NEG}, mn = {POS, POS, POS, POS};

    const __half* mbase = g_mh + (size_t)ch * 128 + lane * 4;

    int e = r0;
    for (; e + 4 <= r1; e += 4) {  // 4-edge unroll for load MLP
        int c0 = ldcs_i(cols + e),     c1 = ldcs_i(cols + e + 1);
        int c2 = ldcs_i(cols + e + 2), c3 = ldcs_i(cols + e + 3);
        float a0 = ldcs_f(vA + e),     a1 = ldcs_f(vA + e + 1);
        float a2 = ldcs_f(vA + e + 2), a3 = ldcs_f(vA + e + 3);
        float b0 = ldcs_f(vC + e),     b1 = ldcs_f(vC + e + 1);
        float b2 = ldcs_f(vC + e + 2), b3 = ldcs_f(vC + e + 3);
        float s0 = (ch == 0) ? a0 : (ch == 1) ? b0 : a0 * b0;
        float s1 = (ch == 0) ? a1 : (ch == 1) ? b1 : a1 * b1;
        float s2 = (ch == 0) ? a2 : (ch == 1) ? b2 : a2 * b2;
        float s3 = (ch == 0) ? a3 : (ch == 1) ? b3 : a3 * b3;
        uint2 u0 = __ldg((const uint2*)(mbase + (size_t)c0 * 384));
        uint2 u1 = __ldg((const uint2*)(mbase + (size_t)c1 * 384));
        uint2 u2 = __ldg((const uint2*)(mbase + (size_t)c2 * 384));
        uint2 u3 = __ldg((const uint2*)(mbase + (size_t)c3 * 384));
        agg_upd(h4tof4(u0), s0, su, sq, mx, mn);
        agg_upd(h4tof4(u1), s1, su, sq, mx, mn);
        agg_upd(h4tof4(u2), s2, su, sq, mx, mn);
        agg_upd(h4tof4(u3), s3, su, sq, mx, mn);
    }
    for (; e < r1; e++) {
        int c = __ldg(cols + e);
        float a = __ldg(vA + e);
        float b = __ldg(vC + e);
        float s = (ch == 0) ? a : (ch == 1) ? b : a * b;
        uint2 u = __ldg((const uint2*)(mbase + (size_t)c * 384));
        agg_upd(h4tof4(u), s, su, sq, mx, mn);
    }

    const int deg = r1 - r0;
    const float inv = 1.f / fmaxf((float)deg, 1.f);
    float4 mean, var, sd;
    mean.x = su.x * inv; mean.y = su.y * inv; mean.z = su.z * inv; mean.w = su.w * inv;
    var.x = fmaxf(sq.x * inv - mean.x * mean.x, 0.f);
    var.y = fmaxf(sq.y * inv - mean.y * mean.y, 0.f);
    var.z = fmaxf(sq.z * inv - mean.z * mean.z, 0.f);
    var.w = fmaxf(sq.w * inv - mean.w * mean.w, 0.f);
    sd.x = sqrtf(var.x + 1e-5f); sd.y = sqrtf(var.y + 1e-5f);
    sd.z = sqrtf(var.z + 1e-5f); sd.w = sqrtf(var.w + 1e-5f);
    if (deg == 0) {
        mx = make_float4(0.f, 0.f, 0.f, 0.f);
        mn = make_float4(0.f, 0.f, 0.f, 0.f);
    }
    // streaming stores: g_fh is read once later; don't evict g_mh from L2
    __half* fb = g_fh + (size_t)node * 1536 + ch * 512 + lane * 4;
    sth4_cs(fb,       mean);
    sth4_cs(fb + 128, mx);
    sth4_cs(fb + 256, mn);
    sth4_cs(fb + 384, sd);
}

// ---------------- output GEMM (fp16 MMA): out = feats @ pw + sum(pna_b) ----------------
__global__ __launch_bounds__(256, 2) void k_out(const float* __restrict__ pb,
                                                float* __restrict__ out, int N) {
    extern __shared__ __align__(16) __half smh[];
    const int bm = blockIdx.x * 128;
    float acc[4][4][4] = {};
    gemm_fp16_core<48, 1536, 1536>(g_fh, g_pwh, acc, bm, N, smh);

    const int lane = threadIdx.x & 31;
    const int wid = threadIdx.x >> 5;
    const int wm = wid >> 2, wn = wid & 3;
    const int tq = lane >> 2, tr = lane & 3;
#pragma unroll
    for (int nt = 0; nt < 4; nt++) {
        const int c0 = wn * 32 + nt * 8 + 2 * tr;
        const float b0 = __ldg(pb + c0) + __ldg(pb + 128 + c0) + __ldg(pb + 256 + c0);
        const float b1 = __ldg(pb + c0 + 1) + __ldg(pb + 128 + c0 + 1) + __ldg(pb + 256 + c0 + 1);
#pragma unroll
        for (int mt = 0; mt < 4; mt++) {
            const int r0 = bm + wm * 64 + mt * 16 + tq;
            if (r0 < N) {
                float2 v = make_float2(acc[mt][nt][0] + b0, acc[mt][nt][1] + b1);
                stcs_f2(&out[(size_t)r0 * 128 + c0], v);
            }
            const int r1 = r0 + 8;
            if (r1 < N) {
                float2 v = make_float2(acc[mt][nt][2] + b0, acc[mt][nt][3] + b1);
                stcs_f2(&out[(size_t)r1 * 128 + c0], v);
            }
        }
    }
}

// ---------------- launch ----------------
extern "C" void kernel_launch(void* const* d_in, const int* in_sizes, int n_in,
                              void* d_out, int out_size) {
    const float* x    = (const float*)d_in[0];
    const int*   rows = (const int*)d_in[1];
    const int*   cols = (const int*)d_in[2];
    const float* vA   = (const float*)d_in[3];
    const float* vC   = (const float*)d_in[4];
    const float* W    = (const float*)d_in[5];
    const float* W2   = (const float*)d_in[6];
    const float* W3   = (const float*)d_in[7];
    const float* pw   = (const float*)d_in[8];  // [3,512,128] == flat [1536,128]
    const float* pb   = (const float*)d_in[9];  // [3,128]
    float* out = (float*)d_out;

    const int N = in_sizes[0] / 128;
    const int E = in_sizes[1];

    // idempotent, not stream-ordered; safe under graph capture
    cudaFuncSetAttribute(k_proj, cudaFuncAttributeMaxDynamicSharedMemorySize, PROJ_SMEM);
    cudaFuncSetAttribute(k_out,  cudaFuncAttributeMaxDynamicSharedMemorySize, GEMM_SMEM);

    __half *wh, *pwh;
    cudaGetSymbolAddress((void**)&wh,  g_wh);
    cudaGetSymbolAddress((void**)&pwh, g_pwh);

    k_rowptr<<<(N + 1 + 255) / 256, 256>>>(rows, E, N);

    dim3 gw3((16384 + 255) / 256, 3);
    k_cvt_w3<<<gw3, 256>>>(W, W2, W3, wh);
    k_cvt_t<<<(196608 + 255) / 256, 256>>>(pw, pwh, 1536, 128);

    k_proj<<<(N + 127) / 128, 256, PROJ_SMEM>>>(x, N);
    const int aggwarps = 3 * N;
    k_agg<<<(aggwarps + 7) / 8, 256>>>(cols, vA, vC, N);
    k_out<<<(N + 127) / 128, 256, GEMM_SMEM>>>(pb, out, N);
}

// round 17
// speedup vs baseline: 1.0477x; 1.0477x over previous
#include <cuda_runtime.h>
#include <cuda_fp16.h>
#include <math_constants.h>
#include <cstdint>

#define NNODES 100000
#define NEDGES 1600000

// ---------------- scratch (static __device__ — no allocs allowed) ----------------
__device__ __half g_mh[(size_t)NNODES * 384];     // projected messages, fp16 [N][3*128]
__device__ __half g_fh[(size_t)NNODES * 1536];    // PNA features, fp16 [N][1536]
__device__ __half g_wh[3 * 128 * 128];            // W|W2|W3 TRANSPOSED [n][k], fp16
__device__ __half g_pwh[128 * 1536];              // pna_w TRANSPOSED [n=128][k=1536], fp16
__device__ int    g_rowptr[NNODES + 1];

// ---------------- cp.async helpers ----------------
__device__ __forceinline__ void cpasync16(unsigned int dst, const void* src) {
    asm volatile("cp.async.cg.shared.global [%0], [%1], 16;\n" :: "r"(dst), "l"(src));
}
__device__ __forceinline__ void cp_commit() {
    asm volatile("cp.async.commit_group;\n" ::);
}
__device__ __forceinline__ void cp_wait1() {
    asm volatile("cp.async.wait_group 1;\n" ::);
}

// ---------------- fp16 MMA m16n8k16 + ldmatrix ----------------
__device__ __forceinline__ void mma_f16(float* d, const unsigned* a, const unsigned* b) {
    asm volatile(
        "mma.sync.aligned.m16n8k16.row.col.f32.f16.f16.f32 "
        "{%0,%1,%2,%3},{%4,%5,%6,%7},{%8,%9},{%0,%1,%2,%3};\n"
        : "+f"(d[0]), "+f"(d[1]), "+f"(d[2]), "+f"(d[3])
        : "r"(a[0]), "r"(a[1]), "r"(a[2]), "r"(a[3]), "r"(b[0]), "r"(b[1]));
}
__device__ __forceinline__ void ldmx4(unsigned& r0, unsigned& r1, unsigned& r2,
                                      unsigned& r3, unsigned addr) {
    asm volatile("ldmatrix.sync.aligned.m8n8.x4.shared.b16 {%0,%1,%2,%3}, [%4];"
                 : "=r"(r0), "=r"(r1), "=r"(r2), "=r"(r3) : "r"(addr));
}

// streaming (evict-first) stores — keep gather working set resident in L2
__device__ __forceinline__ void stcs_u2(void* p, uint2 o) {
    asm volatile("st.global.cs.v2.u32 [%0], {%1,%2};" :: "l"(p), "r"(o.x), "r"(o.y) : "memory");
}
__device__ __forceinline__ void stcs_f2(void* p, float2 v) {
    asm volatile("st.global.cs.v2.f32 [%0], {%1,%2};" :: "l"(p), "f"(v.x), "f"(v.y) : "memory");
}

// ---------------- conversion kernels ----------------
// transpose + convert the 3 projection weights: src [128][128] -> dst [n][k]
__global__ void k_cvt_w3(const float* __restrict__ W, const float* __restrict__ W2,
                         const float* __restrict__ W3, __half* __restrict__ dst) {
    const int slab = blockIdx.y;
    const float* src = (slab == 0) ? W : (slab == 1) ? W2 : W3;
    int i = blockIdx.x * blockDim.x + threadIdx.x;
    if (i < 128 * 128) {
        int k = i >> 7, n = i & 127;
        dst[slab * 16384 + n * 128 + k] = __float2half_rn(src[i]);
    }
}

// transpose + convert: src [K][Ncols] fp32 -> dst [Ncols][K] fp16
__global__ void k_cvt_t(const float* __restrict__ src, __half* __restrict__ dst,
                        int K, int Ncols) {
    int i = blockIdx.x * blockDim.x + threadIdx.x;
    if (i < K * Ncols) {
        int k = i / Ncols, n = i % Ncols;
        dst[(size_t)n * K + k] = __float2half_rn(src[i]);
    }
}

// ---------------- row pointers from sorted rows ----------------
__global__ void k_rowptr(const int* __restrict__ rows, int E, int N) {
    int i = blockIdx.x * blockDim.x + threadIdx.x;
    if (i > N) return;
    int lo = 0, hi = E;
    while (lo < hi) {
        int mid = (lo + hi) >> 1;
        if (__ldg(rows + mid) < i) lo = mid + 1; else hi = mid;
    }
    g_rowptr[i] = lo;
}

// =====================================================================
// fp16 MMA GEMM core (k_out): 128x128 block tile, 8 warps (2x4),
// 64x32 warp tiles, m16n8k16, 3-stage cp.async ring, K-chunk 32.
// =====================================================================
#define RPADH 40                        // halves per smem row (32 data + 8 pad = 80B)
#define STH   (128 * RPADH)             // halves per stage (A or B)
#define GEMM_SMEM (6 * STH * 2)         // 3 stages A + 3 stages B = 60 KB

template <int NK2, int LDA, int LDB>
__device__ __forceinline__ void gemm_fp16_core(
    const __half* __restrict__ Ag, const __half* __restrict__ Bg,
    float acc[4][4][4], int bm, int N, __half* sm) {
    __half* Asb = sm;
    __half* Bsb = sm + 3 * STH;

    const int tid = threadIdx.x;
    const int lane = tid & 31;
    const int wid = tid >> 5;
    const int wm = wid >> 2, wn = wid & 3;

    const int srow = tid >> 1;
    const int shalf = (tid & 1) * 16;

    int gr = bm + srow; if (gr >= N) gr = N - 1;
    const __half* sA = Ag + (size_t)gr * LDA + shalf;
    const __half* sB = Bg + (size_t)srow * LDB + shalf;

    const unsigned dA = (unsigned)__cvta_generic_to_shared(&Asb[srow * RPADH + shalf]);
    const unsigned dB = (unsigned)__cvta_generic_to_shared(&Bsb[srow * RPADH + shalf]);
    const unsigned Abase = (unsigned)__cvta_generic_to_shared(Asb);
    const unsigned Bbase = (unsigned)__cvta_generic_to_shared(Bsb);

    const int arow = ((lane >> 3) & 1) * 8 + (lane & 7);
    const int akof = (lane >> 4) * 8;
    unsigned aoff[4];
#pragma unroll
    for (int mt = 0; mt < 4; mt++)
        aoff[mt] = (unsigned)(((wm * 64 + mt * 16 + arow) * RPADH + akof) * 2);
    const int brow = (lane & 7) + ((lane >> 4) & 1) * 8;
    const int bkof = ((lane >> 3) & 1) * 8;
    unsigned boff[2];
#pragma unroll
    for (int p = 0; p < 2; p++)
        boff[p] = (unsigned)(((wn * 32 + p * 16 + brow) * RPADH + bkof) * 2);

#pragma unroll
    for (int p = 0; p < 2; p++) {
        cpasync16(dA + p * STH * 2, sA + p * 32);
        cpasync16(dA + p * STH * 2 + 16, sA + p * 32 + 8);
        cpasync16(dB + p * STH * 2, sB + p * 32);
        cpasync16(dB + p * STH * 2 + 16, sB + p * 32 + 8);
        cp_commit();
    }

    for (int i = 0; i < NK2; i++) {
        cp_wait1();
        __syncthreads();
        const int nc = i + 2;
        if (nc < NK2) {
            const int sl = nc - (nc / 3) * 3;
            cpasync16(dA + sl * STH * 2, sA + nc * 32);
            cpasync16(dA + sl * STH * 2 + 16, sA + nc * 32 + 8);
            cpasync16(dB + sl * STH * 2, sB + nc * 32);
            cpasync16(dB + sl * STH * 2 + 16, sB + nc * 32 + 8);
        }
        cp_commit();

        const int buf = i - (i / 3) * 3;
        const unsigned sa = Abase + buf * STH * 2;
        const unsigned sb = Bbase + buf * STH * 2;

#pragma unroll
        for (int s = 0; s < 2; s++) {
            unsigned afr[4][4], bfr[4][2];
#pragma unroll
            for (int mt = 0; mt < 4; mt++)
                ldmx4(afr[mt][0], afr[mt][1], afr[mt][2], afr[mt][3],
                      sa + aoff[mt] + s * 32);
#pragma unroll
            for (int p = 0; p < 2; p++)
                ldmx4(bfr[2 * p][0], bfr[2 * p][1], bfr[2 * p + 1][0], bfr[2 * p + 1][1],
                      sb + boff[p] + s * 32);
#pragma unroll
            for (int mt = 0; mt < 4; mt++)
#pragma unroll
                for (int nt = 0; nt < 4; nt++)
                    mma_f16(acc[mt][nt], afr[mt], bfr[nt]);
        }
    }
}

// =====================================================================
// projection GEMM v2 (round-12/15 proven): one block = 128 rows x ALL 3
// slabs. A staged ONCE from fp32 x; per-slab B ring (4 chunks of k32).
// =====================================================================
#define APROW 136                        // halves per A smem row (272B)
#define PROJ_ASZ (128 * APROW)           // halves
#define PROJ_SMEM ((PROJ_ASZ + 3 * STH) * 2)   // 65536 B

__global__ __launch_bounds__(256, 2) void k_proj(const float* __restrict__ x, int N) {
    extern __shared__ __align__(16) __half smh[];
    __half* Ah  = smh;                   // [128][APROW]
    __half* Bsb = smh + PROJ_ASZ;        // [3][128][RPADH]

    const int bm = blockIdx.x * 128;
    const int tid = threadIdx.x;
    const int lane = tid & 31;
    const int wid = tid >> 5;
    const int wm = wid >> 2, wn = wid & 3;
    const int tq = lane >> 2, tr = lane & 3;

    // ---- stage A from fp32 x, converting to fp16 (one time) ----
#pragma unroll
    for (int j = 0; j < 16; j++) {
        int i = tid + j * 256;           // 0..4095 over 128 rows x 32 float4
        int row = i >> 5, c4 = (i & 31) << 2;
        int gr = bm + row; if (gr >= N) gr = N - 1;
        float4 v = *(const float4*)&x[(size_t)gr * 128 + c4];
        __half2 h0 = __floats2half2_rn(v.x, v.y);
        __half2 h1 = __floats2half2_rn(v.z, v.w);
        uint2 o; o.x = *(unsigned*)&h0; o.y = *(unsigned*)&h1;
        *(uint2*)&Ah[row * APROW + c4] = o;
    }

    // B staging mapping
    const int srow = tid >> 1;
    const int shalf = (tid & 1) * 16;
    const unsigned dB = (unsigned)__cvta_generic_to_shared(&Bsb[srow * RPADH + shalf]);
    const unsigned Bbase = (unsigned)__cvta_generic_to_shared(Bsb);
    const unsigned Ahb = (unsigned)__cvta_generic_to_shared(Ah);

    // ldmatrix offsets
    const int arow = ((lane >> 3) & 1) * 8 + (lane & 7);
    const int akof = (lane >> 4) * 8;
    unsigned aoff[4];
#pragma unroll
    for (int mt = 0; mt < 4; mt++)
        aoff[mt] = (unsigned)(((wm * 64 + mt * 16 + arow) * APROW + akof) * 2);
    const int brow = (lane & 7) + ((lane >> 4) & 1) * 8;
    const int bkof = ((lane >> 3) & 1) * 8;
    unsigned boff[2];
#pragma unroll
    for (int p = 0; p < 2; p++)
        boff[p] = (unsigned)(((wn * 32 + p * 16 + brow) * RPADH + bkof) * 2);

    __syncthreads();   // A visible to all (also covers first B-ring use below)

    for (int slab = 0; slab < 3; slab++) {
        const __half* sB = g_wh + slab * 16384 + (size_t)srow * 128 + shalf;
        const int NK2 = 4;
#pragma unroll
        for (int p = 0; p < 2; p++) {
            cpasync16(dB + p * STH * 2, sB + p * 32);
            cpasync16(dB + p * STH * 2 + 16, sB + p * 32 + 8);
            cp_commit();
        }

        float acc[4][4][4] = {};
        for (int i = 0; i < NK2; i++) {
            cp_wait1();
            __syncthreads();
            const int nc = i + 2;
            if (nc < NK2) {
                const int sl = nc - (nc / 3) * 3;
                cpasync16(dB + sl * STH * 2, sB + nc * 32);
                cpasync16(dB + sl * STH * 2 + 16, sB + nc * 32 + 8);
            }
            cp_commit();

            const int buf = i - (i / 3) * 3;
            const unsigned sb = Bbase + buf * STH * 2;
#pragma unroll
            for (int s = 0; s < 2; s++) {
                const int kb = i * 32 + s * 16;   // k base within full row for A
                unsigned afr[4][4], bfr[4][2];
#pragma unroll
                for (int mt = 0; mt < 4; mt++)
                    ldmx4(afr[mt][0], afr[mt][1], afr[mt][2], afr[mt][3],
                          Ahb + aoff[mt] + kb * 2);
#pragma unroll
                for (int p = 0; p < 2; p++)
                    ldmx4(bfr[2 * p][0], bfr[2 * p][1], bfr[2 * p + 1][0],
                          bfr[2 * p + 1][1], sb + boff[p] + s * 32);
#pragma unroll
                for (int mt = 0; mt < 4; mt++)
#pragma unroll
                    for (int nt = 0; nt < 4; nt++)
                        mma_f16(acc[mt][nt], afr[mt], bfr[nt]);
            }
        }
        __syncthreads();   // all reads of B ring done before next slab overwrites

        // epilogue for this slab
#pragma unroll
        for (int nt = 0; nt < 4; nt++) {
            const int c0 = slab * 128 + wn * 32 + nt * 8 + 2 * tr;
#pragma unroll
            for (int mt = 0; mt < 4; mt++) {
                const int r0 = bm + wm * 64 + mt * 16 + tq;
                if (r0 < N) {
                    __half2 h = __floats2half2_rn(acc[mt][nt][0], acc[mt][nt][1]);
                    *(__half2*)&g_mh[(size_t)r0 * 384 + c0] = h;
                }
                const int r1 = r0 + 8;
                if (r1 < N) {
                    __half2 h = __floats2half2_rn(acc[mt][nt][2], acc[mt][nt][3]);
                    *(__half2*)&g_mh[(size_t)r1 * 384 + c0] = h;
                }
            }
        }
    }
}

// ---------------- aggregation: warp-per-(node,channel) segment stats ----------------
__device__ __forceinline__ float4 h4tof4(uint2 u) {
    __half2 a = *(__half2*)&u.x;
    __half2 b = *(__half2*)&u.y;
    float2 fa = __half22float2(a), fb = __half22float2(b);
    return make_float4(fa.x, fa.y, fb.x, fb.y);
}

__device__ __forceinline__ void agg_upd(float4 v, float s, float4& su, float4& sq,
                                        float4& mx, float4& mn) {
    float gx = v.x * s, gy = v.y * s, gz = v.z * s, gw = v.w * s;
    su.x += gx; su.y += gy; su.z += gz; su.w += gw;
    sq.x += gx * gx; sq.y += gy * gy; sq.z += gz * gz; sq.w += gw * gw;
    mx.x = fmaxf(mx.x, gx); mx.y = fmaxf(mx.y, gy); mx.z = fmaxf(mx.z, gz); mx.w = fmaxf(mx.w, gw);
    mn.x = fminf(mn.x, gx); mn.y = fminf(mn.y, gy); mn.z = fminf(mn.z, gz); mn.w = fminf(mn.w, gw);
}

__device__ __forceinline__ void sth4_cs(__half* p, float4 v) {
    __half2 h0 = __floats2half2_rn(v.x, v.y);
    __half2 h1 = __floats2half2_rn(v.z, v.w);
    uint2 o; o.x = *(unsigned*)&h0; o.y = *(unsigned*)&h1;
    stcs_u2(p, o);
}

__global__ __launch_bounds__(256) void k_agg(const int* __restrict__ cols,
                                             const float* __restrict__ vA,
                                             const float* __restrict__ vC, int N) {
    int gw = (blockIdx.x * blockDim.x + threadIdx.x) >> 5;  // global warp
    int lane = threadIdx.x & 31;
    if (gw >= 3 * N) return;
    const int node = gw / 3;
    const int ch = gw - 3 * node;         // 0: vA, 1: vC, 2: vA*vC
    const int r0 = g_rowptr[node], r1 = g_rowptr[node + 1];

    const float NEG = -CUDART_INF_F, POS = CUDART_INF_F;
    float4 su = {0, 0, 0, 0}, sq = {0, 0, 0, 0};
    float4 mx = {NEG, NEG, NEG, NEG}, mn = {POS, POS, POS, POS};

    const __half* mbase = g_mh + (size_t)ch * 128 + lane * 4;

    int e = r0;
    for (; e + 4 <= r1; e += 4) {  // 4-edge unroll for load MLP
        int c0 = __ldg(cols + e),     c1 = __ldg(cols + e + 1);
        int c2 = __ldg(cols + e + 2), c3 = __ldg(cols + e + 3);
        float a0 = __ldg(vA + e),     a1 = __ldg(vA + e + 1);
        float a2 = __ldg(vA + e + 2), a3 = __ldg(vA + e + 3);
        float b0 = __ldg(vC + e),     b1 = __ldg(vC + e + 1);
        float b2 = __ldg(vC + e + 2), b3 = __ldg(vC + e + 3);
        float s0 = (ch == 0) ? a0 : (ch == 1) ? b0 : a0 * b0;
        float s1 = (ch == 0) ? a1 : (ch == 1) ? b1 : a1 * b1;
        float s2 = (ch == 0) ? a2 : (ch == 1) ? b2 : a2 * b2;
        float s3 = (ch == 0) ? a3 : (ch == 1) ? b3 : a3 * b3;
        uint2 u0 = __ldg((const uint2*)(mbase + (size_t)c0 * 384));
        uint2 u1 = __ldg((const uint2*)(mbase + (size_t)c1 * 384));
        uint2 u2 = __ldg((const uint2*)(mbase + (size_t)c2 * 384));
        uint2 u3 = __ldg((const uint2*)(mbase + (size_t)c3 * 384));
        agg_upd(h4tof4(u0), s0, su, sq, mx, mn);
        agg_upd(h4tof4(u1), s1, su, sq, mx, mn);
        agg_upd(h4tof4(u2), s2, su, sq, mx, mn);
        agg_upd(h4tof4(u3), s3, su, sq, mx, mn);
    }
    for (; e < r1; e++) {
        int c = __ldg(cols + e);
        float a = __ldg(vA + e);
        float b = __ldg(vC + e);
        float s = (ch == 0) ? a : (ch == 1) ? b : a * b;
        uint2 u = __ldg((const uint2*)(mbase + (size_t)c * 384));
        agg_upd(h4tof4(u), s, su, sq, mx, mn);
    }

    const int deg = r1 - r0;
    const float inv = 1.f / fmaxf((float)deg, 1.f);
    float4 mean, var, sd;
    mean.x = su.x * inv; mean.y = su.y * inv; mean.z = su.z * inv; mean.w = su.w * inv;
    var.x = fmaxf(sq.x * inv - mean.x * mean.x, 0.f);
    var.y = fmaxf(sq.y * inv - mean.y * mean.y, 0.f);
    var.z = fmaxf(sq.z * inv - mean.z * mean.z, 0.f);
    var.w = fmaxf(sq.w * inv - mean.w * mean.w, 0.f);
    sd.x = sqrtf(var.x + 1e-5f); sd.y = sqrtf(var.y + 1e-5f);
    sd.z = sqrtf(var.z + 1e-5f); sd.w = sqrtf(var.w + 1e-5f);
    if (deg == 0) {
        mx = make_float4(0.f, 0.f, 0.f, 0.f);
        mn = make_float4(0.f, 0.f, 0.f, 0.f);
    }
    // streaming stores: g_fh is read once later; don't evict g_mh from L2
    __half* fb = g_fh + (size_t)node * 1536 + ch * 512 + lane * 4;
    sth4_cs(fb,       mean);
    sth4_cs(fb + 128, mx);
    sth4_cs(fb + 256, mn);
    sth4_cs(fb + 384, sd);
}

// ---------------- output GEMM (fp16 MMA): out = feats @ pw + sum(pna_b) ----------------
__global__ __launch_bounds__(256, 2) void k_out(const float* __restrict__ pb,
                                                float* __restrict__ out, int N) {
    extern __shared__ __align__(16) __half smh[];
    const int bm = blockIdx.x * 128;
    float acc[4][4][4] = {};
    gemm_fp16_core<48, 1536, 1536>(g_fh, g_pwh, acc, bm, N, smh);

    const int lane = threadIdx.x & 31;
    const int wid = threadIdx.x >> 5;
    const int wm = wid >> 2, wn = wid & 3;
    const int tq = lane >> 2, tr = lane & 3;
#pragma unroll
    for (int nt = 0; nt < 4; nt++) {
        const int c0 = wn * 32 + nt * 8 + 2 * tr;
        const float b0 = __ldg(pb + c0) + __ldg(pb + 128 + c0) + __ldg(pb + 256 + c0);
        const float b1 = __ldg(pb + c0 + 1) + __ldg(pb + 128 + c0 + 1) + __ldg(pb + 256 + c0 + 1);
#pragma unroll
        for (int mt = 0; mt < 4; mt++) {
            const int r0 = bm + wm * 64 + mt * 16 + tq;
            if (r0 < N) {
                float2 v = make_float2(acc[mt][nt][0] + b0, acc[mt][nt][1] + b1);
                stcs_f2(&out[(size_t)r0 * 128 + c0], v);
            }
            const int r1 = r0 + 8;
            if (r1 < N) {
                float2 v = make_float2(acc[mt][nt][2] + b0, acc[mt][nt][3] + b1);
                stcs_f2(&out[(size_t)r1 * 128 + c0], v);
            }
        }
    }
}

// ---------------- launch ----------------
extern "C" void kernel_launch(void* const* d_in, const int* in_sizes, int n_in,
                              void* d_out, int out_size) {
    const float* x    = (const float*)d_in[0];
    const int*   rows = (const int*)d_in[1];
    const int*   cols = (const int*)d_in[2];
    const float* vA   = (const float*)d_in[3];
    const float* vC   = (const float*)d_in[4];
    const float* W    = (const float*)d_in[5];
    const float* W2   = (const float*)d_in[6];
    const float* W3   = (const float*)d_in[7];
    const float* pw   = (const float*)d_in[8];  // [3,512,128] == flat [1536,128]
    const float* pb   = (const float*)d_in[9];  // [3,128]
    float* out = (float*)d_out;

    const int N = in_sizes[0] / 128;
    const int E = in_sizes[1];

    // idempotent, not stream-ordered; safe under graph capture
    cudaFuncSetAttribute(k_proj, cudaFuncAttributeMaxDynamicSharedMemorySize, PROJ_SMEM);
    cudaFuncSetAttribute(k_out,  cudaFuncAttributeMaxDynamicSharedMemorySize, GEMM_SMEM);

    __half *wh, *pwh;
    cudaGetSymbolAddress((void**)&wh,  g_wh);
    cudaGetSymbolAddress((void**)&pwh, g_pwh);

    k_rowptr<<<(N + 1 + 255) / 256, 256>>>(rows, E, N);

    dim3 gw3((16384 + 255) / 256, 3);
    k_cvt_w3<<<gw3, 256>>>(W, W2, W3, wh);
    k_cvt_t<<<(196608 + 255) / 256, 256>>>(pw, pwh, 1536, 128);

    k_proj<<<(N + 127) / 128, 256, PROJ_SMEM>>>(x, N);
    const int aggwarps = 3 * N;
    k_agg<<<(aggwarps + 7) / 8, 256>>>(cols, vA, vC, N);
    k_out<<<(N + 127) / 128, 256, GEMM_SMEM>>>(pb, out, N);
}